// round 16
// baseline (speedup 1.0000x reference)
#include <cuda_runtime.h>
#include <math.h>

#define BB 32
#define HH 32
#define KVHH 8
#define DD 128
#define GG 4
#define BLK_SZ 16
#define MAX_BLOCKS 128
#define NSPLIT 8
#define NWARP 8
#define NTHREADS 256
#define NTOK 1          // tokens per warp per stage
#define KV_TILE (NWARP * NTOK)   // 8 tokens per CTA stage
#define NSTG 12         // pipeline depth (prefetch distance 11)
#define TOKB 1024       // bytes per token in smem (K 512 + V 512)

// Scratch (allocation-free: __device__ globals)
__device__ float g_pacc[BB * KVHH * NSPLIT * GG * DD];  // 4 MB split partials
__device__ float g_pl[BB * KVHH * NSPLIT * GG];
__device__ float g_qrot[BB * HH * DD];    // RoPE'd q, scale folded
__device__ float g_krot[BB * KVHH * DD];  // RoPE'd new k

// ---------------- prep: RoPE q and new-k once (R7-proven) ----------------
__global__ __launch_bounds__(DD) void rope_prep_kernel(
    const float* __restrict__ query,
    const float* __restrict__ key,
    const int*   __restrict__ context_lens)
{
    const int b = blockIdx.x;
    const int h = blockIdx.y;
    const int d = threadIdx.x;

    const float pos = (float)context_lens[b];
    const int fi = d & 63;
    const float inv = exp2f(-(float)fi * 0.2076205092783674f);  // log2(10000)/64
    float s, c;
    sincosf(pos * inv, &s, &c);

    if (h < HH) {
        const float* base = query + ((long)b * HH + h) * DD;
        float x = base[d];
        float other = (d < 64) ? -base[d + 64] : base[d - 64];
        g_qrot[((long)b * HH + h) * DD + d] =
            (x * c + other * s) * 0.08838834764831845f;  // D^-0.5
    } else {
        const int kh = h - HH;
        const float* base = key + ((long)b * KVHH + kh) * DD;
        float x = base[d];
        float other = (d < 64) ? -base[d + 64] : base[d - 64];
        g_krot[((long)b * KVHH + kh) * DD + d] = x * c + other * s;
    }
}

// ------- per-token update (R7-proven): no online max, butterfly reduce -------
__device__ __forceinline__ void upd_token(
    const float4& kv, const float4& vv,
    const float4 qv[GG], float l[GG], float4 acc[GG])
{
    float sc[GG];
#pragma unroll
    for (int g = 0; g < GG; g++)
        sc[g] = kv.x * qv[g].x + kv.y * qv[g].y + kv.z * qv[g].z + kv.w * qv[g].w;
#pragma unroll
    for (int off = 16; off > 0; off >>= 1) {
#pragma unroll
        for (int g = 0; g < GG; g++)
            sc[g] += __shfl_xor_sync(0xffffffffu, sc[g], off);
    }
#pragma unroll
    for (int g = 0; g < GG; g++) {
        float p = __expf(sc[g]);
        l[g] += p;
        acc[g].x += p * vv.x;
        acc[g].y += p * vv.y;
        acc[g].z += p * vv.z;
        acc[g].w += p * vv.w;
    }
}

__device__ __forceinline__ void cp16(unsigned smem_addr, const float* gptr) {
    asm volatile("cp.async.cg.shared.global [%0], [%1], 16;"
                 :: "r"(smem_addr), "l"(gptr));
}

// ------- split flash-decode: per-warp 12-deep cp.async pipeline -------
__global__ __launch_bounds__(NTHREADS) void pa_split_kernel(
    const float* __restrict__ value,
    const float* __restrict__ k_cache,
    const float* __restrict__ v_cache,
    const int*   __restrict__ block_table,
    const int*   __restrict__ context_lens)
{
    extern __shared__ float dyn[];
    // sm_kv: [warp][stage][NTOK tokens][256 floats]  (96 KB)
    float* sm_kv = dyn;
    int*   btab  = (int*)(dyn + NWARP * NSTG * NTOK * (TOKB / 4));
    // epilogue buffers alias the kv region (used after a barrier)
    float* sm_wacc = dyn;                         // [NWARP][GG][DD]
    float* sm_wl   = dyn + NWARP * GG * DD;       // [NWARP][GG]

    const int split = blockIdx.x;
    const int kvh   = blockIdx.y;
    const int b     = blockIdx.z;
    const int tid   = threadIdx.x;
    const int lane  = tid & 31;
    const int w     = tid >> 5;

    const int ctx   = context_lens[b];
    const int chunk = (ctx + NSPLIT - 1) / NSPLIT;
    const int s0    = split * chunk;
    const int s1    = min(s0 + chunk, ctx);
    const int last  = ctx - 1;
    const int end   = min(s1, last);

    for (int i = tid; i < MAX_BLOCKS; i += NTHREADS)
        btab[i] = block_table[b * MAX_BLOCKS + i];
    __syncthreads();

    float4 qv[GG];
#pragma unroll
    for (int g = 0; g < GG; g++)
        qv[g] = *(const float4*)&g_qrot[((long)b * HH + kvh * GG + g) * DD + lane * 4];

    float l[GG];
    float4 acc[GG];
#pragma unroll
    for (int g = 0; g < GG; g++) {
        l[g] = 0.f;
        acc[g].x = acc[g].y = acc[g].z = acc[g].w = 0.f;
    }

    const unsigned hoff = (unsigned)kvh * DD + lane * 4;
#define ROWOFF(t) ((((unsigned)btab[(t) >> 4] * BLK_SZ + ((t) & 15)) * (KVHH * DD)) + hoff)

    const int span  = end - s0;
    const int nfull = span > 0 ? span / KV_TILE : 0;

    // warp w's smem slice base (bytes): [w][stage][NTOK][1024B]
    const unsigned my_base = (unsigned)__cvta_generic_to_shared(sm_kv)
                           + (unsigned)w * NSTG * NTOK * TOKB;
    float* my_buf = sm_kv + (size_t)w * NSTG * NTOK * (TOKB / 4);

    // STAGE(tt): warp stages its token of tile tt into slot tt%NSTG
#define STAGE(tt) do {                                                        \
        int S_ = s0 + (tt) * KV_TILE + w * NTOK;                              \
        unsigned sb_ = my_base + (unsigned)((tt) % NSTG) * NTOK * TOKB        \
                     + (unsigned)lane * 16;                                   \
        unsigned ro_ = ROWOFF(S_);                                            \
        cp16(sb_,       k_cache + ro_);                                       \
        cp16(sb_ + 512, v_cache + ro_);                                       \
        asm volatile("cp.async.commit_group;");                               \
    } while (0)
#define STAGE_OR_EMPTY(tt) do {                                               \
        if ((tt) < nfull) STAGE(tt);                                          \
        else asm volatile("cp.async.commit_group;");                          \
    } while (0)

    // prologue: NSTG-1 commits (real or empty) -> constant wait depth in loop
#pragma unroll
    for (int pp = 0; pp < NSTG - 1; pp++)
        STAGE_OR_EMPTY(pp);

    for (int t = 0; t < nfull; t++) {
        STAGE_OR_EMPTY(t + NSTG - 1);
        asm volatile("cp.async.wait_group %0;" :: "n"(NSTG - 1));
        const float* tok = my_buf + (t % NSTG) * NTOK * (TOKB / 4);
        float4 kv = *(const float4*)(tok + lane * 4);
        float4 vv = *(const float4*)(tok + DD + lane * 4);
        upd_token(kv, vv, qv, l, acc);
    }

    // tail: direct-LDG (R7), tokens s0+nfull*8 .. end-1, warp-interleaved
    int s = s0 + nfull * KV_TILE + w;
    while (s < end) {
        unsigned off = ROWOFF(s);
        float4 kv = *(const float4*)(k_cache + off);
        float4 vv = *(const float4*)(v_cache + off);
        upd_token(kv, vv, qv, l, acc);
        s += NWARP;
    }
#undef ROWOFF
#undef STAGE
#undef STAGE_OR_EMPTY

    // in-flight token (RoPE'd new k from scratch, new v from input)
    if (last >= s0 && last < s1 && w == ((last - s0) % NWARP)) {
        float4 kv = *(const float4*)&g_krot[((long)b * KVHH + kvh) * DD + lane * 4];
        float4 vv = *(const float4*)(value + ((long)b * KVHH + kvh) * DD + lane * 4);
        upd_token(kv, vv, qv, l, acc);
    }

    // epilogue: alias wacc/wl into the kv region (all kv reads done)
    __syncthreads();
#pragma unroll
    for (int g = 0; g < GG; g++) {
        if (lane == 0) sm_wl[w * GG + g] = l[g];
        *(float4*)&sm_wacc[(w * GG + g) * DD + lane * 4] = acc[g];
    }
    __syncthreads();

    const long pbase = ((long)(b * KVHH + kvh) * NSPLIT + split) * GG;
    for (int i = tid; i < GG * DD; i += NTHREADS) {
        int g = i >> 7, d = i & 127;
        float t = 0.f;
#pragma unroll
        for (int ww = 0; ww < NWARP; ww++) t += sm_wacc[(ww * GG + g) * DD + d];
        g_pacc[(pbase + g) * DD + d] = t;
    }
    if (tid < GG) {
        float L = 0.f;
#pragma unroll
        for (int ww = 0; ww < NWARP; ww++) L += sm_wl[ww * GG + tid];
        g_pl[pbase + tid] = L;
    }
}

// ---------------- combine (plain sums) ----------------
__global__ __launch_bounds__(DD) void pa_combine_kernel(float* __restrict__ out) {
    const int idx = blockIdx.x;             // B*KVH*G
    const int g   = idx % GG;
    const int kvh = (idx / GG) % KVHH;
    const int b   = idx / (GG * KVHH);
    const int d   = threadIdx.x;

    const long base = ((long)(b * KVHH + kvh) * NSPLIT) * GG + g;
    float L = 0.f, o = 0.f;
#pragma unroll
    for (int s = 0; s < NSPLIT; s++) {
        L += g_pl[base + (long)s * GG];
        o += g_pacc[(base + (long)s * GG) * DD + d];
    }
    out[((long)b * HH + kvh * GG + g) * DD + d] = o / L;
}

extern "C" void kernel_launch(void* const* d_in, const int* in_sizes, int n_in,
                              void* d_out, int out_size) {
    const float* query  = (const float*)d_in[0];
    const float* key    = (const float*)d_in[1];
    const float* value  = (const float*)d_in[2];
    const float* k_cache = (const float*)d_in[3];
    const float* v_cache = (const float*)d_in[4];
    const int*   block_table  = (const int*)d_in[5];
    const int*   context_lens = (const int*)d_in[6];
    float* out = (float*)d_out;

    // dynamic smem: kv pipeline (96 KB) + btab
    const int smem_bytes = NWARP * NSTG * NTOK * TOKB + MAX_BLOCKS * 4;
    static bool attr_set = false;
    if (!attr_set) {
        cudaFuncSetAttribute(pa_split_kernel,
                             cudaFuncAttributeMaxDynamicSharedMemorySize, smem_bytes);
        attr_set = true;
    }

    dim3 pgrid(BB, HH + KVHH);
    rope_prep_kernel<<<pgrid, DD>>>(query, key, context_lens);

    dim3 grid(NSPLIT, KVHH, BB);
    pa_split_kernel<<<grid, NTHREADS, smem_bytes>>>(value, k_cache, v_cache,
                                                    block_table, context_lens);
    pa_combine_kernel<<<BB * KVHH * GG, DD>>>(out);
}